// round 1
// baseline (speedup 1.0000x reference)
#include <cuda_runtime.h>
#include <math.h>

#define NN 50000
#define EE 800000
#define SSED 8192
#define HD 64

// ---------------- scratch (device globals; no allocation allowed) ----------
__device__ float g_deg[3 * NN];
__device__ float g_invdeg[3 * NN];
__device__ float g_S[3][NN * HD];          // per-relation scatter accumulators
__device__ float g_h1[NN * HD];            // layer-1 output (all nodes)
__device__ float g_h2[SSED * HD];          // layer-2 output (first 8192 nodes)
__device__ float g_hs[SSED * HD];          // final node embedding for seeds
__device__ float g_zd1[3 * SSED * 256];
__device__ float g_zd2[3 * SSED * 32];
__device__ float g_yf1[3 * SSED * 256];
__device__ float g_yf2[3 * SSED * 2048];   // 201 MB, static

// ---------------- utility kernels ------------------------------------------
__global__ void k_zero(float* __restrict__ p, long n) {
    long i = (long)blockIdx.x * blockDim.x + threadIdx.x;
    long st = (long)gridDim.x * blockDim.x;
    for (; i < n; i += st) p[i] = 0.f;
}

__global__ void k_deg(const int* __restrict__ d0, const int* __restrict__ d1,
                      const int* __restrict__ d2) {
    long i = (long)blockIdx.x * blockDim.x + threadIdx.x;
    if (i >= 3L * EE) return;
    int r = (int)(i / EE);
    int e = (int)(i % EE);
    const int* d = (r == 0) ? d0 : ((r == 1) ? d1 : d2);
    atomicAdd(&g_deg[r * NN + d[e]], 1.f);
}

__global__ void k_invdeg() {
    int i = blockIdx.x * blockDim.x + threadIdx.x;
    if (i < 3 * NN) g_invdeg[i] = 1.f / fmaxf(g_deg[i], 1.f);
}

// scatter-add h[src] into S[dst], 64 threads per edge
__global__ void k_scatter(const float* __restrict__ h, const int* __restrict__ src,
                          const int* __restrict__ dst, float* __restrict__ S,
                          int dstLimit) {
    long i = (long)blockIdx.x * blockDim.x + threadIdx.x;
    if (i >= (long)EE * HD) return;
    int e = (int)(i >> 6);
    int f = (int)(i & 63);
    int d = dst[e];
    if (d < dstLimit) {
        atomicAdd(&S[(long)d * HD + f], h[(long)src[e] * HD + f]);
    }
}

// out[n][j] = relu(bias[j] + sum_r invdeg[r][n] * sum_k S_r[n][k] * W[r][k][j])
__global__ void k_combine(const float* __restrict__ W, const float* __restrict__ bias,
                          float* __restrict__ out, int nNodes) {
    extern __shared__ float sm[];
    float* sW = sm;                 // 3*64*64 = 12288 floats
    float* sS = sm + 3 * HD * HD;   // 4 nodes * 3 rel * 64
    for (int i = threadIdx.x; i < 3 * HD * HD; i += blockDim.x) sW[i] = W[i];
    __syncthreads();
    const int j = threadIdx.x & 63;
    const int ln = threadIdx.x >> 6;   // 0..3
    for (long n0 = (long)blockIdx.x * 4; n0 < nNodes; n0 += (long)gridDim.x * 4) {
        int n = (int)n0 + ln;
        if (n < nNodes) {
#pragma unroll
            for (int r = 0; r < 3; r++)
                sS[(ln * 3 + r) * HD + j] = g_S[r][(long)n * HD + j] * g_invdeg[r * NN + n];
        }
        __syncthreads();
        if (n < nNodes) {
            float acc = bias[j];
#pragma unroll
            for (int r = 0; r < 3; r++) {
#pragma unroll
                for (int k = 0; k < HD; k++)
                    acc = fmaf(sS[(ln * 3 + r) * HD + k], sW[(r * HD + k) * HD + j], acc);
            }
            out[(long)n * HD + j] = fmaxf(acc, 0.f);
        }
        __syncthreads();
    }
}

// g_hs = leaky_relu(g_h2 @ Wlin + blin) + noise   (8192 rows)
__global__ void k_final(const float* __restrict__ W, const float* __restrict__ bias,
                        const float* __restrict__ noise) {
    __shared__ float sW[HD * HD];
    __shared__ float sS[4 * HD];
    for (int i = threadIdx.x; i < HD * HD; i += blockDim.x) sW[i] = W[i];
    __syncthreads();
    const int j = threadIdx.x & 63;
    const int ln = threadIdx.x >> 6;
    for (int n0 = blockIdx.x * 4; n0 < SSED; n0 += gridDim.x * 4) {
        int n = n0 + ln;
        sS[ln * HD + j] = g_h2[(long)n * HD + j];
        __syncthreads();
        float acc = bias[j];
#pragma unroll
        for (int k = 0; k < HD; k++)
            acc = fmaf(sS[ln * HD + k], sW[k * HD + j], acc);
        float v = (acc > 0.f) ? acc : 0.01f * acc;
        g_hs[(long)n * HD + j] = v + noise[(long)n * HD + j];
        __syncthreads();
    }
}

// ---------------- batched tiled SGEMM + bias + activation ------------------
// C[r] = act(A[r] @ B[r] + bias[r]); A: MxK row-major, B: KxN row-major.
// ACT: 1 = relu, 2 = leaky(0.01), 3 = tanh
template <int ACT>
__global__ void k_sgemm(const float* __restrict__ Aall, const float* __restrict__ Ball,
                        const float* __restrict__ biasAll, float* __restrict__ Call,
                        int M, int N, int K,
                        long sA, long sB, long sBias, long sC, int ldc) {
    const int r = blockIdx.z;
    const float* A = Aall + (long)r * sA;
    const float* B = Ball + (long)r * sB;
    const float* bias = biasAll + (long)r * sBias;
    float* C = Call + (long)r * sC;

    __shared__ float As[16][65];
    __shared__ float Bs[16][64];

    const int tid = threadIdx.x;
    const int bm = blockIdx.y * 64;
    const int bn = blockIdx.x * 64;

    const int aRow = tid >> 2;          // 0..63
    const int aCol = (tid & 3) << 2;    // 0,4,8,12
    const int bRow = tid >> 4;          // 0..15
    const int bCol = (tid & 15) << 2;   // 0..60

    const int tx = tid & 15;
    const int ty = tid >> 4;

    float acc[4][4];
#pragma unroll
    for (int m = 0; m < 4; m++)
#pragma unroll
        for (int n = 0; n < 4; n++) acc[m][n] = 0.f;

    for (int k0 = 0; k0 < K; k0 += 16) {
        // A tile (M%64==0, K%16==0 guaranteed)
        float4 av = *(const float4*)(A + (long)(bm + aRow) * K + k0 + aCol);
        As[aCol + 0][aRow] = av.x;
        As[aCol + 1][aRow] = av.y;
        As[aCol + 2][aRow] = av.z;
        As[aCol + 3][aRow] = av.w;
        // B tile (guard N)
        if (bn + bCol + 3 < N) {
            *(float4*)(&Bs[bRow][bCol]) =
                *(const float4*)(B + (long)(k0 + bRow) * N + bn + bCol);
        } else {
#pragma unroll
            for (int i2 = 0; i2 < 4; i2++)
                Bs[bRow][bCol + i2] =
                    (bn + bCol + i2 < N) ? B[(long)(k0 + bRow) * N + bn + bCol + i2] : 0.f;
        }
        __syncthreads();
#pragma unroll
        for (int k = 0; k < 16; k++) {
            float a0 = As[k][ty * 4 + 0], a1 = As[k][ty * 4 + 1];
            float a2 = As[k][ty * 4 + 2], a3 = As[k][ty * 4 + 3];
            float b0 = Bs[k][tx * 4 + 0], b1 = Bs[k][tx * 4 + 1];
            float b2 = Bs[k][tx * 4 + 2], b3 = Bs[k][tx * 4 + 3];
            acc[0][0] = fmaf(a0, b0, acc[0][0]); acc[0][1] = fmaf(a0, b1, acc[0][1]);
            acc[0][2] = fmaf(a0, b2, acc[0][2]); acc[0][3] = fmaf(a0, b3, acc[0][3]);
            acc[1][0] = fmaf(a1, b0, acc[1][0]); acc[1][1] = fmaf(a1, b1, acc[1][1]);
            acc[1][2] = fmaf(a1, b2, acc[1][2]); acc[1][3] = fmaf(a1, b3, acc[1][3]);
            acc[2][0] = fmaf(a2, b0, acc[2][0]); acc[2][1] = fmaf(a2, b1, acc[2][1]);
            acc[2][2] = fmaf(a2, b2, acc[2][2]); acc[2][3] = fmaf(a2, b3, acc[2][3]);
            acc[3][0] = fmaf(a3, b0, acc[3][0]); acc[3][1] = fmaf(a3, b1, acc[3][1]);
            acc[3][2] = fmaf(a3, b2, acc[3][2]); acc[3][3] = fmaf(a3, b3, acc[3][3]);
        }
        __syncthreads();
    }
#pragma unroll
    for (int m = 0; m < 4; m++) {
        int row = bm + ty * 4 + m;
#pragma unroll
        for (int n = 0; n < 4; n++) {
            int col = bn + tx * 4 + n;
            if (col < N) {
                float v = acc[m][n] + bias[col];
                if (ACT == 1) v = fmaxf(v, 0.f);
                else if (ACT == 2) v = (v > 0.f) ? v : 0.01f * v;
                else if (ACT == 3) v = tanhf(v);
                C[(long)row * ldc + col] = v;
            }
        }
    }
}

// pred_missing head: out[r][s][0] = relu(z2[r][s] . dW3[r] + db3[r])
__global__ void k_dw3(const float* __restrict__ z, const float* __restrict__ W,
                      const float* __restrict__ b, float* __restrict__ out) {
    int i = blockIdx.x * blockDim.x + threadIdx.x;
    if (i >= 3 * SSED) return;
    int r = i / SSED;
    int s = i % SSED;
    const float* zz = z + ((long)r * SSED + s) * 32;
    const float* w = W + r * 32;
    float acc = b[r];
#pragma unroll
    for (int k = 0; k < 32; k++) acc = fmaf(zz[k], w[k], acc);
    out[((long)r * SSED + s) * 321] = fmaxf(acc, 0.f);
}

// ---------------- host launch ----------------------------------------------
extern "C" void kernel_launch(void* const* d_in, const int* in_sizes, int n_in,
                              void* d_out, int out_size) {
    // Logical order: x,noise,seeds,src0,dst0,src1,dst1,src2,dst2,
    //                Wc1,bc1,Wc2,bc2,Wlin,blin,dW1,db1,dW2,db2,dW3,db3,
    //                fW1,fb1,fW2,fb2,fW3,fb3
    static const int MAP_DICT[27] = {0,1,2,3,4,5,6,7,8,9,10,11,12,13,14,15,16,17,18,19,20,21,22,23,24,25,26};
    static const int MAP_SIG[27]  = {0,1,20,21,22,23,24,25,26,2,3,4,5,6,7,8,9,10,11,12,13,14,15,16,17,18,19};
    static const int MAP_ALPHA[27]= {26,21,22,23,12,24,13,25,14,0,3,1,4,2,5,6,9,7,10,8,11,15,18,16,19,17,20};
    const int* MAP = MAP_DICT;
    if (n_in >= 3) {
        if (in_sizes[2] == 12288) MAP = MAP_SIG;       // signature order (W_conv1 third)
        else if (in_sizes[2] == 4096) MAP = MAP_ALPHA; // alphabetical (W_lin third)
    }

    const float* x     = (const float*)d_in[MAP[0]];
    const float* noise = (const float*)d_in[MAP[1]];
    const int* src[3]  = {(const int*)d_in[MAP[3]], (const int*)d_in[MAP[5]], (const int*)d_in[MAP[7]]};
    const int* dst[3]  = {(const int*)d_in[MAP[4]], (const int*)d_in[MAP[6]], (const int*)d_in[MAP[8]]};
    const float* Wc1   = (const float*)d_in[MAP[9]];
    const float* bc1   = (const float*)d_in[MAP[10]];
    const float* Wc2   = (const float*)d_in[MAP[11]];
    const float* bc2   = (const float*)d_in[MAP[12]];
    const float* Wlin  = (const float*)d_in[MAP[13]];
    const float* blin  = (const float*)d_in[MAP[14]];
    const float* dW1   = (const float*)d_in[MAP[15]];
    const float* db1   = (const float*)d_in[MAP[16]];
    const float* dW2   = (const float*)d_in[MAP[17]];
    const float* db2   = (const float*)d_in[MAP[18]];
    const float* dW3   = (const float*)d_in[MAP[19]];
    const float* db3   = (const float*)d_in[MAP[20]];
    const float* fW1   = (const float*)d_in[MAP[21]];
    const float* fb1   = (const float*)d_in[MAP[22]];
    const float* fW2   = (const float*)d_in[MAP[23]];
    const float* fb2   = (const float*)d_in[MAP[24]];
    const float* fW3   = (const float*)d_in[MAP[25]];
    const float* fb3   = (const float*)d_in[MAP[26]];
    float* out = (float*)d_out;

    float *pDeg, *pS, *pH1, *pHs, *pZ1, *pZ2, *pY1, *pY2;
    cudaGetSymbolAddress((void**)&pDeg, g_deg);
    cudaGetSymbolAddress((void**)&pS,   g_S);
    cudaGetSymbolAddress((void**)&pH1,  g_h1);
    cudaGetSymbolAddress((void**)&pHs,  g_hs);
    cudaGetSymbolAddress((void**)&pZ1,  g_zd1);
    cudaGetSymbolAddress((void**)&pZ2,  g_zd2);
    cudaGetSymbolAddress((void**)&pY1,  g_yf1);
    cudaGetSymbolAddress((void**)&pY2,  g_yf2);
    float* pSr[3] = {pS, pS + (long)NN * HD, pS + 2L * NN * HD};

    cudaFuncSetAttribute(k_combine, cudaFuncAttributeMaxDynamicSharedMemorySize, 53248);
    const int SMEM_COMBINE = (3 * HD * HD + 4 * 3 * HD) * sizeof(float);  // 52224

    // degrees (edge structure constant across layers)
    k_zero<<<1024, 256>>>(pDeg, 3L * NN);
    k_deg<<<(3 * EE + 255) / 256, 256>>>(dst[0], dst[1], dst[2]);
    k_invdeg<<<(3 * NN + 255) / 256, 256>>>();

    // ----- conv layer 1 (all N nodes) -----
    k_zero<<<4096, 256>>>(pS, 3L * NN * HD);
    for (int r = 0; r < 3; r++)
        k_scatter<<<(EE * HD) / 256, 256>>>(x, src[r], dst[r], pSr[r], NN);
    k_combine<<<12500, 256, SMEM_COMBINE>>>(Wc1, bc1, pH1, NN);

    // ----- conv layer 2 (only nodes < 8192 feed the output) -----
    for (int r = 0; r < 3; r++)
        k_zero<<<512, 256>>>(pSr[r], (long)SSED * HD);
    for (int r = 0; r < 3; r++)
        k_scatter<<<(EE * HD) / 256, 256>>>(pH1, src[r], dst[r], pSr[r], SSED);
    {
        float* pH2;
        cudaGetSymbolAddress((void**)&pH2, g_h2);
        k_combine<<<2048, 256, SMEM_COMBINE>>>(Wc2, bc2, pH2, SSED);
    }

    // ----- final linear + leaky + noise (seed rows only) -----
    k_final<<<2048, 256>>>(Wlin, blin, noise);

    // ----- decoder: pred_missing branch -----
    dim3 g1(4, SSED / 64, 3);
    k_sgemm<2><<<g1, 256>>>(pHs, dW1, db1, pZ1, SSED, 256, 64,
                            0, (long)64 * 256, 256, (long)SSED * 256, 256);
    dim3 g2(1, SSED / 64, 3);
    k_sgemm<2><<<g2, 256>>>(pZ1, dW2, db2, pZ2, SSED, 32, 256,
                            (long)SSED * 256, (long)256 * 32, 32, (long)SSED * 32, 32);
    k_dw3<<<(3 * SSED + 255) / 256, 256>>>(pZ2, dW3, db3, out);

    // ----- decoder: pred_feat branch -----
    k_sgemm<1><<<g1, 256>>>(pHs, fW1, fb1, pY1, SSED, 256, 64,
                            0, (long)64 * 256, 256, (long)SSED * 256, 256);
    dim3 g3(32, SSED / 64, 3);
    k_sgemm<1><<<g3, 256>>>(pY1, fW2, fb2, pY2, SSED, 2048, 256,
                            (long)SSED * 256, (long)256 * 2048, 2048, (long)SSED * 2048, 2048);
    dim3 g4(5, SSED / 64, 3);
    k_sgemm<3><<<g4, 256>>>(pY2, fW3, fb3, out + 1, SSED, 320, 2048,
                            (long)SSED * 2048, (long)2048 * 320, 320, (long)SSED * 321, 321);
}

// round 2
// speedup vs baseline: 1.4741x; 1.4741x over previous
#include <cuda_runtime.h>
#include <math.h>

#define NN 50000
#define EE 800000
#define SSED 8192
#define HD 64

// ---------------- scratch (device globals; no allocation allowed) ----------
__device__ float g_deg[3 * NN];
__device__ float g_invdeg[3 * NN];
__device__ float g_S[3][NN * HD];          // per-relation scatter accumulators
__device__ float g_h1[NN * HD];            // layer-1 output (all nodes)
__device__ float g_h2[SSED * HD];          // layer-2 output (first 8192 nodes)
__device__ float g_hs[SSED * HD];          // final node embedding for seeds
__device__ float g_zd1[3 * SSED * 256];
__device__ float g_zd2[3 * SSED * 32];
__device__ float g_yf1[3 * SSED * 256];
__device__ float g_yf2[3 * SSED * 2048];

// ---------------- utility kernels ------------------------------------------
__global__ void k_zero(float* __restrict__ p, long n) {
    long i = (long)blockIdx.x * blockDim.x + threadIdx.x;
    long st = (long)gridDim.x * blockDim.x;
    for (; i < n; i += st) p[i] = 0.f;
}

__global__ void k_deg(const int* __restrict__ d0, const int* __restrict__ d1,
                      const int* __restrict__ d2) {
    long i = (long)blockIdx.x * blockDim.x + threadIdx.x;
    if (i >= 3L * EE) return;
    int r = (int)(i / EE);
    int e = (int)(i % EE);
    const int* d = (r == 0) ? d0 : ((r == 1) ? d1 : d2);
    atomicAdd(&g_deg[r * NN + d[e]], 1.f);
}

__global__ void k_invdeg() {
    int i = blockIdx.x * blockDim.x + threadIdx.x;
    if (i < 3 * NN) g_invdeg[i] = 1.f / fmaxf(g_deg[i], 1.f);
}

// scatter-add h[src] into S[dst]: 16 threads per edge, red.global.add.v4.f32
__global__ void k_scatter4(const float* __restrict__ h, const int* __restrict__ src,
                           const int* __restrict__ dst, float* __restrict__ S,
                           int dstLimit) {
    long i = (long)blockIdx.x * blockDim.x + threadIdx.x;
    if (i >= (long)EE * 16) return;
    int e = (int)(i >> 4);
    int f = (int)(i & 15) << 2;
    int d = dst[e];
    if (d < dstLimit) {
        float4 v = *(const float4*)(h + (long)src[e] * HD + f);
        float* p = S + (long)d * HD + f;
        asm volatile("red.global.add.v4.f32 [%0], {%1,%2,%3,%4};"
                     :: "l"(p), "f"(v.x), "f"(v.y), "f"(v.z), "f"(v.w)
                     : "memory");
    }
}

// out[n][j] = relu(bias[j] + sum_r invdeg[r][n] * sum_k S_r[n][k] * W[r][k][j])
__global__ void k_combine(const float* __restrict__ W, const float* __restrict__ bias,
                          float* __restrict__ out, int nNodes) {
    extern __shared__ float sm[];
    float* sW = sm;                 // 3*64*64
    float* sS = sm + 3 * HD * HD;   // 4 nodes * 3 rel * 64
    for (int i = threadIdx.x; i < 3 * HD * HD; i += blockDim.x) sW[i] = W[i];
    __syncthreads();
    const int j = threadIdx.x & 63;
    const int ln = threadIdx.x >> 6;
    for (long n0 = (long)blockIdx.x * 4; n0 < nNodes; n0 += (long)gridDim.x * 4) {
        int n = (int)n0 + ln;
        if (n < nNodes) {
#pragma unroll
            for (int r = 0; r < 3; r++)
                sS[(ln * 3 + r) * HD + j] = g_S[r][(long)n * HD + j] * g_invdeg[r * NN + n];
        }
        __syncthreads();
        if (n < nNodes) {
            float acc = bias[j];
#pragma unroll
            for (int r = 0; r < 3; r++) {
#pragma unroll
                for (int k = 0; k < HD; k++)
                    acc = fmaf(sS[(ln * 3 + r) * HD + k], sW[(r * HD + k) * HD + j], acc);
            }
            out[(long)n * HD + j] = fmaxf(acc, 0.f);
        }
        __syncthreads();
    }
}

// g_hs = leaky_relu(g_h2 @ Wlin + blin) + noise   (8192 rows)
__global__ void k_final(const float* __restrict__ W, const float* __restrict__ bias,
                        const float* __restrict__ noise) {
    __shared__ float sW[HD * HD];
    __shared__ float sS[4 * HD];
    for (int i = threadIdx.x; i < HD * HD; i += blockDim.x) sW[i] = W[i];
    __syncthreads();
    const int j = threadIdx.x & 63;
    const int ln = threadIdx.x >> 6;
    for (int n0 = blockIdx.x * 4; n0 < SSED; n0 += gridDim.x * 4) {
        int n = n0 + ln;
        sS[ln * HD + j] = g_h2[(long)n * HD + j];
        __syncthreads();
        float acc = bias[j];
#pragma unroll
        for (int k = 0; k < HD; k++)
            acc = fmaf(sS[ln * HD + k], sW[k * HD + j], acc);
        float v = (acc > 0.f) ? acc : 0.01f * acc;
        g_hs[(long)n * HD + j] = v + noise[(long)n * HD + j];
        __syncthreads();
    }
}

// ---------------- 128x128x16 double-buffered SGEMM -------------------------
__device__ __forceinline__ void cp16(void* smem, const void* gmem, bool valid) {
    unsigned s = (unsigned)__cvta_generic_to_shared(smem);
    int sz = valid ? 16 : 0;
    asm volatile("cp.async.cg.shared.global [%0], [%1], 16, %2;"
                 :: "r"(s), "l"(gmem), "r"(sz) : "memory");
}

// C[r] = act(A[r] @ B[r] + bias[r]); M%128==0, K%16==0, N%4==0 (N may be any mult of 4)
// ACT: 1 = relu, 2 = leaky(0.01), 3 = tanh
template <int ACT>
__global__ void __launch_bounds__(256, 2)
k_gemm128(const float* __restrict__ Aall, const float* __restrict__ Ball,
          const float* __restrict__ biasAll, float* __restrict__ Call,
          int M, int N, int K, long sA, long sB, long sBias, long sC, int ldc) {
    const int r = blockIdx.z;
    const float* A = Aall + (long)r * sA;
    const float* B = Ball + (long)r * sB;
    const float* bias = biasAll + (long)r * sBias;
    float* C = Call + (long)r * sC;

    __shared__ float As[2][16][128];   // [buf][k][m]
    __shared__ float Bs[2][16][128];   // [buf][k][n]

    const int t = threadIdx.x;
    const long bm = (long)blockIdx.y * 128;
    const int bn = blockIdx.x * 128;

    const int aRow = t >> 2;            // 0..63
    const int aCol = (t & 3) << 2;      // 0,4,8,12
    const int bRow = t >> 5;            // 0..7
    const int bCol = (t & 31) << 2;     // 0..124

    const int tx = t & 15, ty = t >> 4;
    const int tm = ty * 8, tn = tx * 8;

    float acc[8][8];
#pragma unroll
    for (int i = 0; i < 8; i++)
#pragma unroll
        for (int j = 0; j < 8; j++) acc[i][j] = 0.f;

    float4 aReg0, aReg1;
    const int KT = K / 16;
    const bool bValid = (bn + bCol) < N;
    const long bOff = (long)bRow * N + (bValid ? bn + bCol : 0);
    const long bOff2 = bOff + 8L * N;

    // prologue: tile 0
    aReg0 = *(const float4*)(A + (bm + aRow) * (long)K + aCol);
    aReg1 = *(const float4*)(A + (bm + aRow + 64) * (long)K + aCol);
    cp16(&Bs[0][bRow][bCol], B + bOff, bValid);
    cp16(&Bs[0][bRow + 8][bCol], B + bOff2, bValid);
    asm volatile("cp.async.commit_group;" ::: "memory");
    {
        float* a0 = (float*)&aReg0; float* a1 = (float*)&aReg1;
#pragma unroll
        for (int i = 0; i < 4; i++) { As[0][aCol + i][aRow] = a0[i]; As[0][aCol + i][aRow + 64] = a1[i]; }
    }
    asm volatile("cp.async.wait_group 0;" ::: "memory");
    __syncthreads();

    for (int kt = 0; kt < KT; kt++) {
        const int cb = kt & 1, nb = (kt + 1) & 1;
        if (kt + 1 < KT) {
            long ko = (long)(kt + 1) * 16;
            aReg0 = *(const float4*)(A + (bm + aRow) * (long)K + ko + aCol);
            aReg1 = *(const float4*)(A + (bm + aRow + 64) * (long)K + ko + aCol);
            cp16(&Bs[nb][bRow][bCol], B + ko * N + bOff, bValid);
            cp16(&Bs[nb][bRow + 8][bCol], B + ko * N + bOff2, bValid);
            asm volatile("cp.async.commit_group;" ::: "memory");
        }
#pragma unroll
        for (int k = 0; k < 16; k++) {
            float4 a0 = *(const float4*)&As[cb][k][tm];
            float4 a1 = *(const float4*)&As[cb][k][tm + 4];
            float4 b0 = *(const float4*)&Bs[cb][k][tn];
            float4 b1 = *(const float4*)&Bs[cb][k][tn + 4];
            float a[8] = {a0.x, a0.y, a0.z, a0.w, a1.x, a1.y, a1.z, a1.w};
            float b[8] = {b0.x, b0.y, b0.z, b0.w, b1.x, b1.y, b1.z, b1.w};
#pragma unroll
            for (int i = 0; i < 8; i++)
#pragma unroll
                for (int j = 0; j < 8; j++)
                    acc[i][j] = fmaf(a[i], b[j], acc[i][j]);
        }
        if (kt + 1 < KT) {
            float* a0 = (float*)&aReg0; float* a1 = (float*)&aReg1;
#pragma unroll
            for (int i = 0; i < 4; i++) { As[nb][aCol + i][aRow] = a0[i]; As[nb][aCol + i][aRow + 64] = a1[i]; }
            asm volatile("cp.async.wait_group 0;" ::: "memory");
        }
        __syncthreads();
    }

    // epilogue
    const bool vec = ((ldc & 3) == 0) && ((((size_t)C) & 15) == 0);
#pragma unroll
    for (int i = 0; i < 8; i++) {
        long row = bm + tm + i;
        if (vec) {
#pragma unroll
            for (int j4 = 0; j4 < 2; j4++) {
                int col = bn + tn + j4 * 4;
                if (col < N) {
                    float4 v;
                    float* vv = (float*)&v;
#pragma unroll
                    for (int j = 0; j < 4; j++) {
                        float u = acc[i][j4 * 4 + j] + bias[col + j];
                        if (ACT == 1) u = fmaxf(u, 0.f);
                        else if (ACT == 2) u = (u > 0.f) ? u : 0.01f * u;
                        else u = tanhf(u);
                        vv[j] = u;
                    }
                    *(float4*)(C + row * ldc + col) = v;
                }
            }
        } else {
#pragma unroll
            for (int j = 0; j < 8; j++) {
                int col = bn + tn + j;
                if (col < N) {
                    float u = acc[i][j] + bias[col];
                    if (ACT == 1) u = fmaxf(u, 0.f);
                    else if (ACT == 2) u = (u > 0.f) ? u : 0.01f * u;
                    else u = tanhf(u);
                    C[row * ldc + col] = u;
                }
            }
        }
    }
}

// ---------------- small 64x64 SGEMM (kept for N=32 case) -------------------
template <int ACT>
__global__ void k_sgemm(const float* __restrict__ Aall, const float* __restrict__ Ball,
                        const float* __restrict__ biasAll, float* __restrict__ Call,
                        int M, int N, int K,
                        long sA, long sB, long sBias, long sC, int ldc) {
    const int r = blockIdx.z;
    const float* A = Aall + (long)r * sA;
    const float* B = Ball + (long)r * sB;
    const float* bias = biasAll + (long)r * sBias;
    float* C = Call + (long)r * sC;

    __shared__ float As[16][65];
    __shared__ float Bs[16][64];

    const int tid = threadIdx.x;
    const int bm = blockIdx.y * 64;
    const int bn = blockIdx.x * 64;

    const int aRow = tid >> 2;
    const int aCol = (tid & 3) << 2;
    const int bRow = tid >> 4;
    const int bCol = (tid & 15) << 2;

    const int tx = tid & 15;
    const int ty = tid >> 4;

    float acc[4][4];
#pragma unroll
    for (int m = 0; m < 4; m++)
#pragma unroll
        for (int n = 0; n < 4; n++) acc[m][n] = 0.f;

    for (int k0 = 0; k0 < K; k0 += 16) {
        float4 av = *(const float4*)(A + (long)(bm + aRow) * K + k0 + aCol);
        As[aCol + 0][aRow] = av.x;
        As[aCol + 1][aRow] = av.y;
        As[aCol + 2][aRow] = av.z;
        As[aCol + 3][aRow] = av.w;
        if (bn + bCol + 3 < N) {
            *(float4*)(&Bs[bRow][bCol]) =
                *(const float4*)(B + (long)(k0 + bRow) * N + bn + bCol);
        } else {
#pragma unroll
            for (int i2 = 0; i2 < 4; i2++)
                Bs[bRow][bCol + i2] =
                    (bn + bCol + i2 < N) ? B[(long)(k0 + bRow) * N + bn + bCol + i2] : 0.f;
        }
        __syncthreads();
#pragma unroll
        for (int k = 0; k < 16; k++) {
            float a0 = As[k][ty * 4 + 0], a1 = As[k][ty * 4 + 1];
            float a2 = As[k][ty * 4 + 2], a3 = As[k][ty * 4 + 3];
            float b0 = Bs[k][tx * 4 + 0], b1 = Bs[k][tx * 4 + 1];
            float b2 = Bs[k][tx * 4 + 2], b3 = Bs[k][tx * 4 + 3];
            acc[0][0] = fmaf(a0, b0, acc[0][0]); acc[0][1] = fmaf(a0, b1, acc[0][1]);
            acc[0][2] = fmaf(a0, b2, acc[0][2]); acc[0][3] = fmaf(a0, b3, acc[0][3]);
            acc[1][0] = fmaf(a1, b0, acc[1][0]); acc[1][1] = fmaf(a1, b1, acc[1][1]);
            acc[1][2] = fmaf(a1, b2, acc[1][2]); acc[1][3] = fmaf(a1, b3, acc[1][3]);
            acc[2][0] = fmaf(a2, b0, acc[2][0]); acc[2][1] = fmaf(a2, b1, acc[2][1]);
            acc[2][2] = fmaf(a2, b2, acc[2][2]); acc[2][3] = fmaf(a2, b3, acc[2][3]);
            acc[3][0] = fmaf(a3, b0, acc[3][0]); acc[3][1] = fmaf(a3, b1, acc[3][1]);
            acc[3][2] = fmaf(a3, b2, acc[3][2]); acc[3][3] = fmaf(a3, b3, acc[3][3]);
        }
        __syncthreads();
    }
#pragma unroll
    for (int m = 0; m < 4; m++) {
        int row = bm + ty * 4 + m;
#pragma unroll
        for (int n = 0; n < 4; n++) {
            int col = bn + tx * 4 + n;
            if (col < N) {
                float v = acc[m][n] + bias[col];
                if (ACT == 1) v = fmaxf(v, 0.f);
                else if (ACT == 2) v = (v > 0.f) ? v : 0.01f * v;
                else if (ACT == 3) v = tanhf(v);
                C[(long)row * ldc + col] = v;
            }
        }
    }
}

// pred_missing head: out[r][s][0] = relu(z2[r][s] . dW3[r] + db3[r])
__global__ void k_dw3(const float* __restrict__ z, const float* __restrict__ W,
                      const float* __restrict__ b, float* __restrict__ out) {
    int i = blockIdx.x * blockDim.x + threadIdx.x;
    if (i >= 3 * SSED) return;
    int r = i / SSED;
    int s = i % SSED;
    const float* zz = z + ((long)r * SSED + s) * 32;
    const float* w = W + r * 32;
    float acc = b[r];
#pragma unroll
    for (int k = 0; k < 32; k++) acc = fmaf(zz[k], w[k], acc);
    out[((long)r * SSED + s) * 321] = fmaxf(acc, 0.f);
}

// ---------------- host launch ----------------------------------------------
extern "C" void kernel_launch(void* const* d_in, const int* in_sizes, int n_in,
                              void* d_out, int out_size) {
    static const int MAP_DICT[27] = {0,1,2,3,4,5,6,7,8,9,10,11,12,13,14,15,16,17,18,19,20,21,22,23,24,25,26};
    static const int MAP_SIG[27]  = {0,1,20,21,22,23,24,25,26,2,3,4,5,6,7,8,9,10,11,12,13,14,15,16,17,18,19};
    static const int MAP_ALPHA[27]= {26,21,22,23,12,24,13,25,14,0,3,1,4,2,5,6,9,7,10,8,11,15,18,16,19,17,20};
    const int* MAP = MAP_DICT;
    if (n_in >= 3) {
        if (in_sizes[2] == 12288) MAP = MAP_SIG;
        else if (in_sizes[2] == 4096) MAP = MAP_ALPHA;
    }

    const float* x     = (const float*)d_in[MAP[0]];
    const float* noise = (const float*)d_in[MAP[1]];
    const int* src[3]  = {(const int*)d_in[MAP[3]], (const int*)d_in[MAP[5]], (const int*)d_in[MAP[7]]};
    const int* dst[3]  = {(const int*)d_in[MAP[4]], (const int*)d_in[MAP[6]], (const int*)d_in[MAP[8]]};
    const float* Wc1   = (const float*)d_in[MAP[9]];
    const float* bc1   = (const float*)d_in[MAP[10]];
    const float* Wc2   = (const float*)d_in[MAP[11]];
    const float* bc2   = (const float*)d_in[MAP[12]];
    const float* Wlin  = (const float*)d_in[MAP[13]];
    const float* blin  = (const float*)d_in[MAP[14]];
    const float* dW1   = (const float*)d_in[MAP[15]];
    const float* db1   = (const float*)d_in[MAP[16]];
    const float* dW2   = (const float*)d_in[MAP[17]];
    const float* db2   = (const float*)d_in[MAP[18]];
    const float* dW3   = (const float*)d_in[MAP[19]];
    const float* db3   = (const float*)d_in[MAP[20]];
    const float* fW1   = (const float*)d_in[MAP[21]];
    const float* fb1   = (const float*)d_in[MAP[22]];
    const float* fW2   = (const float*)d_in[MAP[23]];
    const float* fb2   = (const float*)d_in[MAP[24]];
    const float* fW3   = (const float*)d_in[MAP[25]];
    const float* fb3   = (const float*)d_in[MAP[26]];
    float* out = (float*)d_out;

    float *pDeg, *pS, *pH1, *pH2, *pHs, *pZ1, *pZ2, *pY1, *pY2;
    cudaGetSymbolAddress((void**)&pDeg, g_deg);
    cudaGetSymbolAddress((void**)&pS,   g_S);
    cudaGetSymbolAddress((void**)&pH1,  g_h1);
    cudaGetSymbolAddress((void**)&pH2,  g_h2);
    cudaGetSymbolAddress((void**)&pHs,  g_hs);
    cudaGetSymbolAddress((void**)&pZ1,  g_zd1);
    cudaGetSymbolAddress((void**)&pZ2,  g_zd2);
    cudaGetSymbolAddress((void**)&pY1,  g_yf1);
    cudaGetSymbolAddress((void**)&pY2,  g_yf2);
    float* pSr[3] = {pS, pS + (long)NN * HD, pS + 2L * NN * HD};

    cudaFuncSetAttribute(k_combine, cudaFuncAttributeMaxDynamicSharedMemorySize, 53248);
    const int SMEM_COMBINE = (3 * HD * HD + 4 * 3 * HD) * sizeof(float);

    // degrees
    k_zero<<<1024, 256>>>(pDeg, 3L * NN);
    k_deg<<<(3 * EE + 255) / 256, 256>>>(dst[0], dst[1], dst[2]);
    k_invdeg<<<(3 * NN + 255) / 256, 256>>>();

    // ----- conv layer 1 (all N nodes) -----
    k_zero<<<4096, 256>>>(pS, 3L * NN * HD);
    for (int r = 0; r < 3; r++)
        k_scatter4<<<(EE * 16) / 256, 256>>>(x, src[r], dst[r], pSr[r], NN);
    k_combine<<<12500, 256, SMEM_COMBINE>>>(Wc1, bc1, pH1, NN);

    // ----- conv layer 2 (only nodes < 8192 feed the output) -----
    for (int r = 0; r < 3; r++)
        k_zero<<<512, 256>>>(pSr[r], (long)SSED * HD);
    for (int r = 0; r < 3; r++)
        k_scatter4<<<(EE * 16) / 256, 256>>>(pH1, src[r], dst[r], pSr[r], SSED);
    k_combine<<<2048, 256, SMEM_COMBINE>>>(Wc2, bc2, pH2, SSED);

    // ----- final linear + leaky + noise -----
    k_final<<<2048, 256>>>(Wlin, blin, noise);

    // ----- decoder: pred_missing branch -----
    dim3 g1(2, SSED / 128, 3);   // N=256
    k_gemm128<2><<<g1, 256>>>(pHs, dW1, db1, pZ1, SSED, 256, 64,
                              0, (long)64 * 256, 256, (long)SSED * 256, 256);
    dim3 g2(1, SSED / 64, 3);    // N=32 small kernel
    k_sgemm<2><<<g2, 256>>>(pZ1, dW2, db2, pZ2, SSED, 32, 256,
                            (long)SSED * 256, (long)256 * 32, 32, (long)SSED * 32, 32);
    k_dw3<<<(3 * SSED + 255) / 256, 256>>>(pZ2, dW3, db3, out);

    // ----- decoder: pred_feat branch -----
    k_gemm128<1><<<g1, 256>>>(pHs, fW1, fb1, pY1, SSED, 256, 64,
                              0, (long)64 * 256, 256, (long)SSED * 256, 256);
    dim3 g3(16, SSED / 128, 3);  // N=2048
    k_gemm128<1><<<g3, 256>>>(pY1, fW2, fb2, pY2, SSED, 2048, 256,
                              (long)SSED * 256, (long)256 * 2048, 2048, (long)SSED * 2048, 2048);
    dim3 g4(3, SSED / 128, 3);   // N=320 (ceil 320/128 = 3)
    k_gemm128<3><<<g4, 256>>>(pY2, fW3, fb3, out + 1, SSED, 320, 2048,
                              (long)SSED * 2048, (long)2048 * 320, 320, (long)SSED * 321, 321);
}

// round 3
// speedup vs baseline: 2.5196x; 1.7093x over previous
#include <cuda_runtime.h>
#include <math.h>

#define NN 50000
#define EE 800000
#define SSED 8192
#define HD 64

// ---------------- scratch (device globals; no allocation allowed) ----------
__device__ float g_deg[3 * NN];
__device__ float g_invdeg[3 * NN];
__device__ float g_S[3][NN * HD];
__device__ float g_h1[NN * HD];
__device__ float g_h2[SSED * HD];
__device__ float g_hs[SSED * HD];
__device__ float g_zd1[3 * SSED * 256];
__device__ float g_zd2[3 * SSED * 32];
__device__ float g_yf1[3 * SSED * 256];
__device__ float g_yf2[3 * SSED * 2048];

// ---------------- utility kernels ------------------------------------------
__global__ void k_zero(float* __restrict__ p, long n) {
    long i = (long)blockIdx.x * blockDim.x + threadIdx.x;
    long st = (long)gridDim.x * blockDim.x;
    for (; i < n; i += st) p[i] = 0.f;
}

__global__ void k_deg(const int* __restrict__ d0, const int* __restrict__ d1,
                      const int* __restrict__ d2) {
    long i = (long)blockIdx.x * blockDim.x + threadIdx.x;
    if (i >= 3L * EE) return;
    int r = (int)(i / EE);
    int e = (int)(i % EE);
    const int* d = (r == 0) ? d0 : ((r == 1) ? d1 : d2);
    atomicAdd(&g_deg[r * NN + d[e]], 1.f);
}

__global__ void k_invdeg() {
    int i = blockIdx.x * blockDim.x + threadIdx.x;
    if (i < 3 * NN) g_invdeg[i] = 1.f / fmaxf(g_deg[i], 1.f);
}

// scatter-add h[src] into S[dst]: 16 threads per edge, red.global.add.v4.f32
__global__ void k_scatter4(const float* __restrict__ h, const int* __restrict__ src,
                           const int* __restrict__ dst, float* __restrict__ S,
                           int dstLimit) {
    long i = (long)blockIdx.x * blockDim.x + threadIdx.x;
    if (i >= (long)EE * 16) return;
    int e = (int)(i >> 4);
    int f = (int)(i & 15) << 2;
    int d = dst[e];
    if (d < dstLimit) {
        float4 v = *(const float4*)(h + (long)src[e] * HD + f);
        float* p = S + (long)d * HD + f;
        asm volatile("red.global.add.v4.f32 [%0], {%1,%2,%3,%4};"
                     :: "l"(p), "f"(v.x), "f"(v.y), "f"(v.z), "f"(v.w)
                     : "memory");
    }
}

// out[n][j] = relu(bias[j] + sum_r invdeg[r][n] * sum_k S_r[n][k] * W[r][k][j])
__global__ void k_combine(const float* __restrict__ W, const float* __restrict__ bias,
                          float* __restrict__ out, int nNodes) {
    extern __shared__ float sm[];
    float* sW = sm;
    float* sS = sm + 3 * HD * HD;
    for (int i = threadIdx.x; i < 3 * HD * HD; i += blockDim.x) sW[i] = W[i];
    __syncthreads();
    const int j = threadIdx.x & 63;
    const int ln = threadIdx.x >> 6;
    for (long n0 = (long)blockIdx.x * 4; n0 < nNodes; n0 += (long)gridDim.x * 4) {
        int n = (int)n0 + ln;
        if (n < nNodes) {
#pragma unroll
            for (int r = 0; r < 3; r++)
                sS[(ln * 3 + r) * HD + j] = g_S[r][(long)n * HD + j] * g_invdeg[r * NN + n];
        }
        __syncthreads();
        if (n < nNodes) {
            float acc = bias[j];
#pragma unroll
            for (int r = 0; r < 3; r++) {
#pragma unroll
                for (int k = 0; k < HD; k++)
                    acc = fmaf(sS[(ln * 3 + r) * HD + k], sW[(r * HD + k) * HD + j], acc);
            }
            out[(long)n * HD + j] = fmaxf(acc, 0.f);
        }
        __syncthreads();
    }
}

// g_hs = leaky_relu(g_h2 @ Wlin + blin) + noise
__global__ void k_final(const float* __restrict__ W, const float* __restrict__ bias,
                        const float* __restrict__ noise) {
    __shared__ float sW[HD * HD];
    __shared__ float sS[4 * HD];
    for (int i = threadIdx.x; i < HD * HD; i += blockDim.x) sW[i] = W[i];
    __syncthreads();
    const int j = threadIdx.x & 63;
    const int ln = threadIdx.x >> 6;
    for (int n0 = blockIdx.x * 4; n0 < SSED; n0 += gridDim.x * 4) {
        int n = n0 + ln;
        sS[ln * HD + j] = g_h2[(long)n * HD + j];
        __syncthreads();
        float acc = bias[j];
#pragma unroll
        for (int k = 0; k < HD; k++)
            acc = fmaf(sS[ln * HD + k], sW[k * HD + j], acc);
        float v = (acc > 0.f) ? acc : 0.01f * acc;
        g_hs[(long)n * HD + j] = v + noise[(long)n * HD + j];
        __syncthreads();
    }
}

// ---------------- TF32 tensor-core GEMM -------------------------------------
__device__ __forceinline__ void cp16(void* smem, const void* gmem, bool valid) {
    unsigned s = (unsigned)__cvta_generic_to_shared(smem);
    int sz = valid ? 16 : 0;
    asm volatile("cp.async.cg.shared.global [%0], [%1], 16, %2;"
                 :: "r"(s), "l"(gmem), "r"(sz) : "memory");
}
__device__ __forceinline__ unsigned tf32(float f) {
    unsigned u;
    asm("cvt.rna.tf32.f32 %0, %1;" : "=r"(u) : "f"(f));
    return u;
}
__device__ __forceinline__ void mma8(float* c, const unsigned* a, const unsigned* b) {
    asm volatile("mma.sync.aligned.m16n8k8.row.col.f32.tf32.tf32.f32 "
                 "{%0,%1,%2,%3}, {%4,%5,%6,%7}, {%8,%9}, {%0,%1,%2,%3};"
                 : "+f"(c[0]), "+f"(c[1]), "+f"(c[2]), "+f"(c[3])
                 : "r"(a[0]), "r"(a[1]), "r"(a[2]), "r"(a[3]), "r"(b[0]), "r"(b[1]));
}

// C[r] = act(A[r] @ B[r] + bias[r]); A MxK row-major, B KxN row-major.
// Requires M%128==0, K%16==0. ACT: 1=relu, 2=leaky(0.01), 3=tanh
template <int ACT>
__global__ void __launch_bounds__(256, 2)
k_tgemm(const float* __restrict__ Aall, const float* __restrict__ Ball,
        const float* __restrict__ biasAll, float* __restrict__ Call,
        int M, int N, int K, long sA, long sB, long sBias, long sC, int ldc) {
    const int r = blockIdx.z;
    const float* A = Aall + (long)r * sA;
    const float* B = Ball + (long)r * sB;
    const float* bias = biasAll + (long)r * sBias;
    float* C = Call + (long)r * sC;

    __shared__ float As[2][128][20];   // [buf][m][k], stride 20 -> conflict-free frags
    __shared__ float Bs[2][16][136];   // [buf][k][n], stride 136 -> conflict-free frags

    const int t = threadIdx.x;
    const int lane = t & 31;
    const int warp = t >> 5;
    const int wm = (warp >> 2) * 64;   // warp row base within CTA tile
    const int wn = (warp & 3) * 32;    // warp col base within CTA tile
    const long bm = (long)blockIdx.y * 128;
    const int bn = blockIdx.x * 128;

    const int aRow = t >> 2;           // 0..63
    const int aCol = (t & 3) << 2;     // 0,4,8,12
    const int bRow = t >> 5;           // 0..7
    const int bCol = (t & 31) << 2;    // 0..124
    const bool bValid = (bn + bCol) < N;
    const int bnc = bValid ? bn + bCol : 0;

    const int gid = lane >> 2;         // 0..7
    const int tig = lane & 3;          // 0..3

    float acc[4][4][4];
#pragma unroll
    for (int i = 0; i < 4; i++)
#pragma unroll
        for (int j = 0; j < 4; j++)
#pragma unroll
            for (int c = 0; c < 4; c++) acc[i][j][c] = 0.f;

    const int KT = K / 16;

    // prologue
    {
        cp16(&As[0][aRow][aCol], A + (bm + aRow) * (long)K + aCol, true);
        cp16(&As[0][aRow + 64][aCol], A + (bm + aRow + 64) * (long)K + aCol, true);
        cp16(&Bs[0][bRow][bCol], B + (long)bRow * N + bnc, bValid);
        cp16(&Bs[0][bRow + 8][bCol], B + (long)(bRow + 8) * N + bnc, bValid);
        asm volatile("cp.async.commit_group;" ::: "memory");
        asm volatile("cp.async.wait_group 0;" ::: "memory");
        __syncthreads();
    }

    for (int kt = 0; kt < KT; kt++) {
        const int cb = kt & 1, nb = (kt + 1) & 1;
        if (kt + 1 < KT) {
            long ko = (long)(kt + 1) * 16;
            cp16(&As[nb][aRow][aCol], A + (bm + aRow) * (long)K + ko + aCol, true);
            cp16(&As[nb][aRow + 64][aCol], A + (bm + aRow + 64) * (long)K + ko + aCol, true);
            cp16(&Bs[nb][bRow][bCol], B + (ko + bRow) * (long)N + bnc, bValid);
            cp16(&Bs[nb][bRow + 8][bCol], B + (ko + bRow + 8) * (long)N + bnc, bValid);
            asm volatile("cp.async.commit_group;" ::: "memory");
        }
#pragma unroll
        for (int k8 = 0; k8 < 2; k8++) {
            const int k0 = k8 * 8;
            unsigned a[4][4], b[4][2];
#pragma unroll
            for (int tm = 0; tm < 4; tm++) {
                int m = wm + tm * 16 + gid;
                a[tm][0] = tf32(As[cb][m][k0 + tig]);
                a[tm][1] = tf32(As[cb][m + 8][k0 + tig]);
                a[tm][2] = tf32(As[cb][m][k0 + tig + 4]);
                a[tm][3] = tf32(As[cb][m + 8][k0 + tig + 4]);
            }
#pragma unroll
            for (int tn = 0; tn < 4; tn++) {
                int n = wn + tn * 8 + gid;
                b[tn][0] = tf32(Bs[cb][k0 + tig][n]);
                b[tn][1] = tf32(Bs[cb][k0 + tig + 4][n]);
            }
#pragma unroll
            for (int tm = 0; tm < 4; tm++)
#pragma unroll
                for (int tn = 0; tn < 4; tn++)
                    mma8(acc[tm][tn], a[tm], b[tn]);
        }
        if (kt + 1 < KT)
            asm volatile("cp.async.wait_group 0;" ::: "memory");
        __syncthreads();
    }

    // epilogue
#pragma unroll
    for (int tm = 0; tm < 4; tm++) {
        long row0 = bm + wm + tm * 16 + gid;
#pragma unroll
        for (int tn = 0; tn < 4; tn++) {
            int col = bn + wn + tn * 8 + tig * 2;
            if (col < N) {
                float bs0 = bias[col], bs1 = bias[col + 1];
#pragma unroll
                for (int h = 0; h < 2; h++) {
                    long row = row0 + h * 8;
                    float u0 = acc[tm][tn][h * 2 + 0] + bs0;
                    float u1 = acc[tm][tn][h * 2 + 1] + bs1;
                    if (ACT == 1) { u0 = fmaxf(u0, 0.f); u1 = fmaxf(u1, 0.f); }
                    else if (ACT == 2) { u0 = (u0 > 0.f) ? u0 : 0.01f * u0;
                                         u1 = (u1 > 0.f) ? u1 : 0.01f * u1; }
                    else { u0 = tanhf(u0); u1 = tanhf(u1); }
                    C[row * ldc + col] = u0;
                    C[row * ldc + col + 1] = u1;
                }
            }
        }
    }
}

// ---------------- small 64x64 SGEMM (N=32 case) ----------------------------
template <int ACT>
__global__ void k_sgemm(const float* __restrict__ Aall, const float* __restrict__ Ball,
                        const float* __restrict__ biasAll, float* __restrict__ Call,
                        int M, int N, int K,
                        long sA, long sB, long sBias, long sC, int ldc) {
    const int r = blockIdx.z;
    const float* A = Aall + (long)r * sA;
    const float* B = Ball + (long)r * sB;
    const float* bias = biasAll + (long)r * sBias;
    float* C = Call + (long)r * sC;

    __shared__ float As[16][65];
    __shared__ float Bs[16][64];

    const int tid = threadIdx.x;
    const int bm = blockIdx.y * 64;
    const int bn = blockIdx.x * 64;

    const int aRow = tid >> 2;
    const int aCol = (tid & 3) << 2;
    const int bRow = tid >> 4;
    const int bCol = (tid & 15) << 2;

    const int tx = tid & 15;
    const int ty = tid >> 4;

    float acc[4][4];
#pragma unroll
    for (int m = 0; m < 4; m++)
#pragma unroll
        for (int n = 0; n < 4; n++) acc[m][n] = 0.f;

    for (int k0 = 0; k0 < K; k0 += 16) {
        float4 av = *(const float4*)(A + (long)(bm + aRow) * K + k0 + aCol);
        As[aCol + 0][aRow] = av.x;
        As[aCol + 1][aRow] = av.y;
        As[aCol + 2][aRow] = av.z;
        As[aCol + 3][aRow] = av.w;
        if (bn + bCol + 3 < N) {
            *(float4*)(&Bs[bRow][bCol]) =
                *(const float4*)(B + (long)(k0 + bRow) * N + bn + bCol);
        } else {
#pragma unroll
            for (int i2 = 0; i2 < 4; i2++)
                Bs[bRow][bCol + i2] =
                    (bn + bCol + i2 < N) ? B[(long)(k0 + bRow) * N + bn + bCol + i2] : 0.f;
        }
        __syncthreads();
#pragma unroll
        for (int k = 0; k < 16; k++) {
            float a0 = As[k][ty * 4 + 0], a1 = As[k][ty * 4 + 1];
            float a2 = As[k][ty * 4 + 2], a3 = As[k][ty * 4 + 3];
            float b0 = Bs[k][tx * 4 + 0], b1 = Bs[k][tx * 4 + 1];
            float b2 = Bs[k][tx * 4 + 2], b3 = Bs[k][tx * 4 + 3];
            acc[0][0] = fmaf(a0, b0, acc[0][0]); acc[0][1] = fmaf(a0, b1, acc[0][1]);
            acc[0][2] = fmaf(a0, b2, acc[0][2]); acc[0][3] = fmaf(a0, b3, acc[0][3]);
            acc[1][0] = fmaf(a1, b0, acc[1][0]); acc[1][1] = fmaf(a1, b1, acc[1][1]);
            acc[1][2] = fmaf(a1, b2, acc[1][2]); acc[1][3] = fmaf(a1, b3, acc[1][3]);
            acc[2][0] = fmaf(a2, b0, acc[2][0]); acc[2][1] = fmaf(a2, b1, acc[2][1]);
            acc[2][2] = fmaf(a2, b2, acc[2][2]); acc[2][3] = fmaf(a2, b3, acc[2][3]);
            acc[3][0] = fmaf(a3, b0, acc[3][0]); acc[3][1] = fmaf(a3, b1, acc[3][1]);
            acc[3][2] = fmaf(a3, b2, acc[3][2]); acc[3][3] = fmaf(a3, b3, acc[3][3]);
        }
        __syncthreads();
    }
#pragma unroll
    for (int m = 0; m < 4; m++) {
        int row = bm + ty * 4 + m;
#pragma unroll
        for (int n = 0; n < 4; n++) {
            int col = bn + tx * 4 + n;
            if (col < N) {
                float v = acc[m][n] + bias[col];
                if (ACT == 1) v = fmaxf(v, 0.f);
                else if (ACT == 2) v = (v > 0.f) ? v : 0.01f * v;
                else if (ACT == 3) v = tanhf(v);
                C[(long)row * ldc + col] = v;
            }
        }
    }
}

// pred_missing head
__global__ void k_dw3(const float* __restrict__ z, const float* __restrict__ W,
                      const float* __restrict__ b, float* __restrict__ out) {
    int i = blockIdx.x * blockDim.x + threadIdx.x;
    if (i >= 3 * SSED) return;
    int r = i / SSED;
    int s = i % SSED;
    const float* zz = z + ((long)r * SSED + s) * 32;
    const float* w = W + r * 32;
    float acc = b[r];
#pragma unroll
    for (int k = 0; k < 32; k++) acc = fmaf(zz[k], w[k], acc);
    out[((long)r * SSED + s) * 321] = fmaxf(acc, 0.f);
}

// ---------------- host launch ----------------------------------------------
extern "C" void kernel_launch(void* const* d_in, const int* in_sizes, int n_in,
                              void* d_out, int out_size) {
    static const int MAP_DICT[27] = {0,1,2,3,4,5,6,7,8,9,10,11,12,13,14,15,16,17,18,19,20,21,22,23,24,25,26};
    static const int MAP_SIG[27]  = {0,1,20,21,22,23,24,25,26,2,3,4,5,6,7,8,9,10,11,12,13,14,15,16,17,18,19};
    static const int MAP_ALPHA[27]= {26,21,22,23,12,24,13,25,14,0,3,1,4,2,5,6,9,7,10,8,11,15,18,16,19,17,20};
    const int* MAP = MAP_DICT;
    if (n_in >= 3) {
        if (in_sizes[2] == 12288) MAP = MAP_SIG;
        else if (in_sizes[2] == 4096) MAP = MAP_ALPHA;
    }

    const float* x     = (const float*)d_in[MAP[0]];
    const float* noise = (const float*)d_in[MAP[1]];
    const int* src[3]  = {(const int*)d_in[MAP[3]], (const int*)d_in[MAP[5]], (const int*)d_in[MAP[7]]};
    const int* dst[3]  = {(const int*)d_in[MAP[4]], (const int*)d_in[MAP[6]], (const int*)d_in[MAP[8]]};
    const float* Wc1   = (const float*)d_in[MAP[9]];
    const float* bc1   = (const float*)d_in[MAP[10]];
    const float* Wc2   = (const float*)d_in[MAP[11]];
    const float* bc2   = (const float*)d_in[MAP[12]];
    const float* Wlin  = (const float*)d_in[MAP[13]];
    const float* blin  = (const float*)d_in[MAP[14]];
    const float* dW1   = (const float*)d_in[MAP[15]];
    const float* db1   = (const float*)d_in[MAP[16]];
    const float* dW2   = (const float*)d_in[MAP[17]];
    const float* db2   = (const float*)d_in[MAP[18]];
    const float* dW3   = (const float*)d_in[MAP[19]];
    const float* db3   = (const float*)d_in[MAP[20]];
    const float* fW1   = (const float*)d_in[MAP[21]];
    const float* fb1   = (const float*)d_in[MAP[22]];
    const float* fW2   = (const float*)d_in[MAP[23]];
    const float* fb2   = (const float*)d_in[MAP[24]];
    const float* fW3   = (const float*)d_in[MAP[25]];
    const float* fb3   = (const float*)d_in[MAP[26]];
    float* out = (float*)d_out;

    float *pDeg, *pS, *pH1, *pH2, *pHs, *pZ1, *pZ2, *pY1, *pY2;
    cudaGetSymbolAddress((void**)&pDeg, g_deg);
    cudaGetSymbolAddress((void**)&pS,   g_S);
    cudaGetSymbolAddress((void**)&pH1,  g_h1);
    cudaGetSymbolAddress((void**)&pH2,  g_h2);
    cudaGetSymbolAddress((void**)&pHs,  g_hs);
    cudaGetSymbolAddress((void**)&pZ1,  g_zd1);
    cudaGetSymbolAddress((void**)&pZ2,  g_zd2);
    cudaGetSymbolAddress((void**)&pY1,  g_yf1);
    cudaGetSymbolAddress((void**)&pY2,  g_yf2);
    float* pSr[3] = {pS, pS + (long)NN * HD, pS + 2L * NN * HD};

    cudaFuncSetAttribute(k_combine, cudaFuncAttributeMaxDynamicSharedMemorySize, 53248);
    const int SMEM_COMBINE = (3 * HD * HD + 4 * 3 * HD) * sizeof(float);

    // degrees
    k_zero<<<1024, 256>>>(pDeg, 3L * NN);
    k_deg<<<(3 * EE + 255) / 256, 256>>>(dst[0], dst[1], dst[2]);
    k_invdeg<<<(3 * NN + 255) / 256, 256>>>();

    // ----- conv layer 1 -----
    k_zero<<<4096, 256>>>(pS, 3L * NN * HD);
    for (int r = 0; r < 3; r++)
        k_scatter4<<<(EE * 16) / 256, 256>>>(x, src[r], dst[r], pSr[r], NN);
    k_combine<<<12500, 256, SMEM_COMBINE>>>(Wc1, bc1, pH1, NN);

    // ----- conv layer 2 (only dst < 8192 matters) -----
    for (int r = 0; r < 3; r++)
        k_zero<<<512, 256>>>(pSr[r], (long)SSED * HD);
    for (int r = 0; r < 3; r++)
        k_scatter4<<<(EE * 16) / 256, 256>>>(pH1, src[r], dst[r], pSr[r], SSED);
    k_combine<<<2048, 256, SMEM_COMBINE>>>(Wc2, bc2, pH2, SSED);

    // ----- final linear -----
    k_final<<<2048, 256>>>(Wlin, blin, noise);

    // ----- decoder: pred_missing -----
    dim3 g1(2, SSED / 128, 3);    // N=256
    k_tgemm<2><<<g1, 256>>>(pHs, dW1, db1, pZ1, SSED, 256, 64,
                            0, (long)64 * 256, 256, (long)SSED * 256, 256);
    dim3 g2(1, SSED / 64, 3);     // N=32
    k_sgemm<2><<<g2, 256>>>(pZ1, dW2, db2, pZ2, SSED, 32, 256,
                            (long)SSED * 256, (long)256 * 32, 32, (long)SSED * 32, 32);
    k_dw3<<<(3 * SSED + 255) / 256, 256>>>(pZ2, dW3, db3, out);

    // ----- decoder: pred_feat -----
    k_tgemm<1><<<g1, 256>>>(pHs, fW1, fb1, pY1, SSED, 256, 64,
                            0, (long)64 * 256, 256, (long)SSED * 256, 256);
    dim3 g3(16, SSED / 128, 3);   // N=2048
    k_tgemm<1><<<g3, 256>>>(pY1, fW2, fb2, pY2, SSED, 2048, 256,
                            (long)SSED * 256, (long)256 * 2048, 2048, (long)SSED * 2048, 2048);
    dim3 g4(3, SSED / 128, 3);    // N=320
    k_tgemm<3><<<g4, 256>>>(pY2, fW3, fb3, out + 1, SSED, 320, 2048,
                            (long)SSED * 2048, (long)2048 * 320, 320, (long)SSED * 321, 321);
}